// round 11
// baseline (speedup 1.0000x reference)
#include <cuda_runtime.h>
#include <cuda_bf16.h>
#include <cstdint>
#include <cmath>

// ---------------- problem constants ----------------
#define Nn 8192
#define Mm 50

#define CTA_ROWS 64
#define GRID (Nn / CTA_ROWS)   // 128
#define THREADS 256            // 8 warps: 2 sets x 4 warps; sets split chunks by parity

// weight fragment image: per chunk, uint2 entries
//   W1: [h(2)][ks(6)][nt(8)][lane(32)]  -> 3072 uint2
//   W2: [h(2)][ks(4)][nt(8)][lane(32)]  -> 2048 uint2, at offset 3072
#define WCH_U2 5120
#define W2_OFF 3072
#define WCH_B  (WCH_U2 * 8)    // 40960 bytes per chunk

// smem layout (bytes): 4 weight buffers (2 per set) + D2 exchange + consts
#define SM_W   0                          // 4 * 40960 = 163840
#define SM_EX  163840                     // 256 threads * 33 floats * 4 = 33792
#define SM_W0  (SM_EX + 33792)            // 197632
#define SM_B1  (SM_W0 + 2048)
#define SM_B2  (SM_B1 + 2048)
#define SM_TH  (SM_B2 + 256)
#define SMEM_BYTES (SM_TH + 256)          // 202240

__device__ __align__(16) uint2 gWf[8][WCH_U2];

// ---------------- helpers ----------------
__device__ __forceinline__ float ftanh(float x) {
    float y; asm("tanh.approx.f32 %0, %1;" : "=f"(y) : "f"(x)); return y;
}
__device__ __forceinline__ void cp16(uint32_t dst, const void* src) {
    asm volatile("cp.async.cg.shared.global [%0], [%1], 16;" :: "r"(dst), "l"(src));
}
#define CP_COMMIT() asm volatile("cp.async.commit_group;" ::: "memory")
#define CP_WAIT0()  asm volatile("cp.async.wait_group 0;" ::: "memory")
__device__ __forceinline__ void barset(int id) {
    asm volatile("bar.sync %0, 128;" :: "r"(id) : "memory");
}

// split two fp32 (xe = even-k, xo = odd-k) into bf16x2 hi and lo words, even in low half
__device__ __forceinline__ void split_pair(float xe, float xo, uint32_t& whi, uint32_t& wlo) {
    uint32_t h;
    asm("cvt.rn.bf16x2.f32 %0, %1, %2;" : "=r"(h) : "f"(xo), "f"(xe));
    float fe = __uint_as_float(h << 16);
    float fo = __uint_as_float(h & 0xFFFF0000u);
    uint32_t lw;
    asm("cvt.rn.bf16x2.f32 %0, %1, %2;" : "=r"(lw) : "f"(xo - fo), "f"(xe - fe));
    whi = h; wlo = lw;
}

__device__ __forceinline__ void mma16816(float d[4],
    uint32_t a0, uint32_t a1, uint32_t a2, uint32_t a3, uint2 b) {
    asm volatile(
        "mma.sync.aligned.m16n8k16.row.col.f32.bf16.bf16.f32 "
        "{%0,%1,%2,%3}, {%4,%5,%6,%7}, {%8,%9}, {%0,%1,%2,%3};"
        : "+f"(d[0]), "+f"(d[1]), "+f"(d[2]), "+f"(d[3])
        : "r"(a0), "r"(a1), "r"(a2), "r"(a3), "r"(b.x), "r"(b.y));
}

// ---------------- setup: prepack weights into B-fragment order, bf16 hi/lo ----
__global__ void build_frags(const float* __restrict__ W1, const float* __restrict__ W2) {
    int tid = blockIdx.x * blockDim.x + threadIdx.x;
    int stride = gridDim.x * blockDim.x;

    for (int i = tid; i < 24576; i += stride) {
        int l  = i & 31;
        int nt = (i >> 5) & 7;
        int r8 = i >> 8;
        int ks = r8 % 6;
        int h  = (r8 / 6) & 1;
        int ch = i / 3072;
        int n  = ch * 64 + nt * 8 + (l >> 2);
        int k0 = ks * 16 + (l & 3) * 2;
        float v[4] = { W1[(size_t)(1 + k0) * 512 + n], W1[(size_t)(2 + k0) * 512 + n],
                       W1[(size_t)(9 + k0) * 512 + n], W1[(size_t)(10 + k0) * 512 + n] };
        uint32_t p[2];
        #pragma unroll
        for (int q = 0; q < 2; q++) {
            float a = v[2*q], bq = v[2*q + 1];
            if (h) {
                a  -= __bfloat162float(__float2bfloat16(a));
                bq -= __bfloat162float(__float2bfloat16(bq));
            }
            p[q] = (uint32_t)__bfloat16_as_ushort(__float2bfloat16(a))
                 | ((uint32_t)__bfloat16_as_ushort(__float2bfloat16(bq)) << 16);
        }
        gWf[ch][((h * 6 + ks) * 8 + nt) * 32 + l] = make_uint2(p[0], p[1]);
    }

    for (int i = tid; i < 16384; i += stride) {
        int l  = i & 31;
        int nt = (i >> 5) & 7;
        int r8 = i >> 8;
        int ks = r8 % 4;
        int h  = (r8 / 4) & 1;
        int ch = i / 2048;
        int n  = nt * 8 + (l >> 2);
        int k0 = ch * 64 + ks * 16 + (l & 3) * 2;
        float v[4] = { W2[(size_t)k0 * 64 + n],       W2[(size_t)(k0 + 1) * 64 + n],
                       W2[(size_t)(k0 + 8) * 64 + n], W2[(size_t)(k0 + 9) * 64 + n] };
        uint32_t p[2];
        #pragma unroll
        for (int q = 0; q < 2; q++) {
            float a = v[2*q], bq = v[2*q + 1];
            if (h) {
                a  -= __bfloat162float(__float2bfloat16(a));
                bq -= __bfloat162float(__float2bfloat16(bq));
            }
            p[q] = (uint32_t)__bfloat16_as_ushort(__float2bfloat16(a))
                 | ((uint32_t)__bfloat16_as_ushort(__float2bfloat16(bq)) << 16);
        }
        gWf[ch][W2_OFF + ((h * 4 + ks) * 8 + nt) * 32 + l] = make_uint2(p[0], p[1]);
    }
}

// ---------------- main rollout: 2 chunk-parity sets per CTA ----------------
__global__ void __launch_bounds__(THREADS, 1) rollout_mma(
    const float* __restrict__ X0, const float* __restrict__ V0,
    const float* __restrict__ Y,  const float* __restrict__ theta,
    const float* __restrict__ W1, const float* __restrict__ b1,
    const float* __restrict__ W2, const float* __restrict__ b2,
    const float* __restrict__ noise, const int* __restrict__ obs_index,
    float* __restrict__ out)
{
    extern __shared__ __align__(16) unsigned char smem[];
    uint2* sW  = (uint2*)(smem + SM_W);
    float* sEX = (float*)(smem + SM_EX);
    float* sW0 = (float*)(smem + SM_W0);
    float* sB1 = (float*)(smem + SM_B1);
    float* sB2 = (float*)(smem + SM_B2);
    float* sTH = (float*)(smem + SM_TH);
    const uint32_t sb = (uint32_t)__cvta_generic_to_shared(smem);

    const int tid  = threadIdx.x;
    const int setid = tid >> 7;             // 0 = even chunks, 1 = odd chunks
    const int wl   = tid & 127;             // index within set
    const int l    = tid & 31;
    const int w4   = (tid >> 5) & 3;        // row-warp within set
    const int g = l >> 2, c = l & 3;
    const int row0 = blockIdx.x * CTA_ROWS;
    const int rA = row0 + w4 * 16 + g;
    const int rB = rA + 8;

    const float dt = 1.0f / (float)Mm;
    const float sqdt = sqrtf(dt);
    const int obs = *obs_index;

    for (int i = tid; i < 512; i += THREADS) { sW0[i] = W1[i]; sB1[i] = b1[i]; }
    if (tid < 64) { sB2[tid] = b2[tid]; sTH[tid] = theta[tid]; }

    // X fp32 state (duplicated across sets; identical deterministic updates)
    float X[8][4];
    #pragma unroll
    for (int j = 0; j < 8; j++) {
        int col = c * 2 + 8 * j;
        float2 va = *(const float2*)(X0 + (size_t)rA * 64 + col);
        float2 vb = *(const float2*)(X0 + (size_t)rB * 64 + col);
        X[j][0] = va.x; X[j][1] = va.y; X[j][2] = vb.x; X[j][3] = vb.y;
    }

    // Y A-fragments (static): GEMM1 k-steps 4,5
    uint32_t Yhi[2][4], Ylo[2][4];
    #pragma unroll
    for (int ks = 0; ks < 2; ks++)
        #pragma unroll
        for (int r = 0; r < 2; r++) {
            int yc = ks * 16 + c * 2 + r * 8;
            float2 ya = *(const float2*)(Y + (size_t)rA * 32 + (size_t)obs * 32 + yc);
            float2 yb = *(const float2*)(Y + (size_t)rB * 32 + (size_t)obs * 32 + yc);
            split_pair(ya.x, ya.y, Yhi[ks][2*r],     Ylo[ks][2*r]);
            split_pair(yb.x, yb.y, Yhi[ks][2*r + 1], Ylo[ks][2*r + 1]);
        }

    uint32_t Xhi[4][4], Xlo[4][4];
    auto build_xfrags = [&]() {
        #pragma unroll
        for (int ks = 0; ks < 4; ks++) {
            split_pair(X[2*ks][0],     X[2*ks][1],     Xhi[ks][0], Xlo[ks][0]);
            split_pair(X[2*ks][2],     X[2*ks][3],     Xhi[ks][1], Xlo[ks][1]);
            split_pair(X[2*ks + 1][0], X[2*ks + 1][1], Xhi[ks][2], Xlo[ks][2]);
            split_pair(X[2*ks + 1][2], X[2*ks + 1][3], Xhi[ks][3], Xlo[ks][3]);
        }
    };
    build_xfrags();

    float vA = 0.0f, vB = 0.0f;

    __syncthreads();   // consts staged before any set reads them

    // prime: my set's first chunk into my buffer 0
    {
        const uint2* src = gWf[setid];
        uint32_t dst = sb + SM_W + (uint32_t)(setid * 2) * WCH_B;
        for (int i = wl; i < WCH_U2 / 2; i += 128) cp16(dst + i * 16, src + i * 2);
        CP_COMMIT();
    }

    for (int m = 0; m < Mm; m++) {
        const float s = (float)m * dt;
        float D2[8][4];
        #pragma unroll
        for (int nt = 0; nt < 8; nt++)
            #pragma unroll
            for (int i = 0; i < 4; i++) D2[nt][i] = 0.0f;

        for (int i4 = 0; i4 < 4; i4++) {
            const int ch = 2 * i4 + setid;
            CP_WAIT0();                 // my cps done (current buffer loaded)
            barset(1 + setid);          // whole set past prev chunk & cps visible

            // prefetch my set's next chunk into my other buffer
            {
                const uint2* src = gWf[(ch + 2) & 7];
                uint32_t dst = sb + SM_W + (uint32_t)(setid * 2 + ((i4 + 1) & 1)) * WCH_B;
                for (int i = wl; i < WCH_U2 / 2; i += 128) cp16(dst + i * 16, src + i * 2);
                CP_COMMIT();
            }

            const uint2* wb = sW + (setid * 2 + (i4 & 1)) * WCH_U2;

            // ---- GEMM1: C1[16x64] = [X|Y] @ W1chunk, 3-term split ----
            float C1[8][4];
            #pragma unroll
            for (int nt = 0; nt < 8; nt++)
                #pragma unroll
                for (int i = 0; i < 4; i++) C1[nt][i] = 0.0f;

            #pragma unroll
            for (int ks = 0; ks < 6; ks++) {
                uint32_t AH[4], AL[4];
                #pragma unroll
                for (int q = 0; q < 4; q++) {
                    AH[q] = (ks < 4) ? Xhi[ks & 3][q] : Yhi[ks & 1][q];
                    AL[q] = (ks < 4) ? Xlo[ks & 3][q] : Ylo[ks & 1][q];
                }
                uint2 bh = wb[(ks * 8) * 32 + l];
                uint2 bl = wb[((6 + ks) * 8) * 32 + l];
                #pragma unroll
                for (int nt = 0; nt < 8; nt++) {
                    uint2 bh2, bl2;
                    if (nt < 7) {
                        bh2 = wb[(ks * 8 + nt + 1) * 32 + l];
                        bl2 = wb[((6 + ks) * 8 + nt + 1) * 32 + l];
                    }
                    mma16816(C1[nt], AH[0], AH[1], AH[2], AH[3], bh);
                    mma16816(C1[nt], AL[0], AL[1], AL[2], AL[3], bh);
                    mma16816(C1[nt], AH[0], AH[1], AH[2], AH[3], bl);
                    bh = bh2; bl = bl2;
                }
            }

            // ---- bias + tanh + split -> GEMM2 (C1 frags are A frags) ----
            const int cbase = ch * 64;
            #pragma unroll
            for (int ks2 = 0; ks2 < 4; ks2++) {
                int col0 = cbase + ks2 * 16 + c * 2;
                float2 w0a = *(const float2*)&sW0[col0];
                float2 b1a = *(const float2*)&sB1[col0];
                float2 w0b = *(const float2*)&sW0[col0 + 8];
                float2 b1b = *(const float2*)&sB1[col0 + 8];
                float hb0 = fmaf(s, w0a.x, b1a.x), hb1 = fmaf(s, w0a.y, b1a.y);
                float hb2 = fmaf(s, w0b.x, b1b.x), hb3 = fmaf(s, w0b.y, b1b.y);
                float h00 = ftanh(C1[2*ks2][0] + hb0);
                float h01 = ftanh(C1[2*ks2][1] + hb1);
                float h02 = ftanh(C1[2*ks2][2] + hb0);
                float h03 = ftanh(C1[2*ks2][3] + hb1);
                float h10 = ftanh(C1[2*ks2 + 1][0] + hb2);
                float h11 = ftanh(C1[2*ks2 + 1][1] + hb3);
                float h12 = ftanh(C1[2*ks2 + 1][2] + hb2);
                float h13 = ftanh(C1[2*ks2 + 1][3] + hb3);
                uint32_t ah0, ah1, ah2, ah3, al0, al1, al2, al3;
                split_pair(h00, h01, ah0, al0);
                split_pair(h02, h03, ah1, al1);
                split_pair(h10, h11, ah2, al2);
                split_pair(h12, h13, ah3, al3);

                uint2 bh = wb[W2_OFF + (ks2 * 8) * 32 + l];
                uint2 bl = wb[W2_OFF + ((4 + ks2) * 8) * 32 + l];
                #pragma unroll
                for (int nt = 0; nt < 8; nt++) {
                    uint2 bh2, bl2;
                    if (nt < 7) {
                        bh2 = wb[W2_OFF + (ks2 * 8 + nt + 1) * 32 + l];
                        bl2 = wb[W2_OFF + ((4 + ks2) * 8 + nt + 1) * 32 + l];
                    }
                    mma16816(D2[nt], ah0, ah1, ah2, ah3, bh);
                    mma16816(D2[nt], al0, al1, al2, al3, bh);
                    mma16816(D2[nt], ah0, ah1, ah2, ah3, bl);
                    bh = bh2; bl = bl2;
                }
            }
        }

        // ---- noise loads (LDG, issued early to hide latency behind exchange) ----
        float2 nA[8], nB[8];
        #pragma unroll
        for (int nt = 0; nt < 8; nt++) {
            int col = c * 2 + 8 * nt;
            nA[nt] = *(const float2*)(noise + ((size_t)m * Nn + rA) * 64 + col);
            nB[nt] = *(const float2*)(noise + ((size_t)m * Nn + rB) * 64 + col);
        }

        // ---- D2 exchange between sets (padded stride 33: conflict-free) ----
        {
            float* exw = sEX + tid * 33;
            #pragma unroll
            for (int nt = 0; nt < 8; nt++)
                #pragma unroll
                for (int q = 0; q < 4; q++) exw[nt * 4 + q] = D2[nt][q];
        }
        __syncthreads();
        {
            const float* exr = sEX + (tid ^ 128) * 33;
            #pragma unroll
            for (int nt = 0; nt < 8; nt++)
                #pragma unroll
                for (int q = 0; q < 4; q++) D2[nt][q] += exr[nt * 4 + q];
        }
        __syncthreads();   // EX free for next step

        // ---- step epilogue: Z -> V, X update (both sets, identical) ----
        #pragma unroll
        for (int nt = 0; nt < 8; nt++) {
            int col = c * 2 + 8 * nt;
            float2 b2v = *(const float2*)&sB2[col];
            float2 thv = *(const float2*)&sTH[col];
            float z0 = D2[nt][0] + b2v.x, z1 = D2[nt][1] + b2v.y;
            float z2 = D2[nt][2] + b2v.x, z3 = D2[nt][3] + b2v.y;
            float wa0 = sqdt * nA[nt].x, wa1 = sqdt * nA[nt].y;
            float wb0 = sqdt * nB[nt].x, wb1 = sqdt * nB[nt].y;
            vA += z0 * wa0 + z1 * wa1 - 0.5f * dt * (z0 * z0 + z1 * z1);
            vB += z2 * wb0 + z3 * wb1 - 0.5f * dt * (z2 * z2 + z3 * z3);
            X[nt][0] += dt * (thv.x - X[nt][0] - z0) + wa0;
            X[nt][1] += dt * (thv.y - X[nt][1] - z1) + wa1;
            X[nt][2] += dt * (thv.x - X[nt][2] - z2) + wb0;
            X[nt][3] += dt * (thv.y - X[nt][3] - z3) + wb1;
        }
        build_xfrags();
    }

    // ---- output (set E only; it covers all 64 rows) ----
    if (setid == 0) {
        #pragma unroll
        for (int nt = 0; nt < 8; nt++) {
            int col = c * 2 + 8 * nt;
            *(float2*)(out + (size_t)rA * 64 + col) = make_float2(X[nt][0], X[nt][1]);
            *(float2*)(out + (size_t)rB * 64 + col) = make_float2(X[nt][2], X[nt][3]);
        }
        vA += __shfl_down_sync(0xffffffffu, vA, 2, 4);
        vA += __shfl_down_sync(0xffffffffu, vA, 1, 4);
        vB += __shfl_down_sync(0xffffffffu, vB, 2, 4);
        vB += __shfl_down_sync(0xffffffffu, vB, 1, 4);
        if (c == 0) {
            out[(size_t)Nn * 64 + rA] = V0[rA] + vA;
            out[(size_t)Nn * 64 + rB] = V0[rB] + vB;
        }
    }
    CP_WAIT0();
}

extern "C" void kernel_launch(void* const* d_in, const int* in_sizes, int n_in,
                              void* d_out, int out_size)
{
    (void)in_sizes; (void)n_in; (void)out_size;
    cudaFuncSetAttribute(rollout_mma,
                         cudaFuncAttributeMaxDynamicSharedMemorySize, SMEM_BYTES);

    build_frags<<<64, 256>>>((const float*)d_in[4], (const float*)d_in[6]);
    rollout_mma<<<GRID, THREADS, SMEM_BYTES>>>(
        (const float*)d_in[0], (const float*)d_in[1], (const float*)d_in[2],
        (const float*)d_in[3], (const float*)d_in[4], (const float*)d_in[5],
        (const float*)d_in[6], (const float*)d_in[7], (const float*)d_in[8],
        (const int*)d_in[9],   (float*)d_out);
}

// round 12
// speedup vs baseline: 1.0011x; 1.0011x over previous
#include <cuda_runtime.h>
#include <cuda_bf16.h>
#include <cstdint>
#include <cmath>

// ---------------- problem constants ----------------
#define Nn 8192
#define Mm 50

#define CTA_ROWS 64
#define GRID (Nn / CTA_ROWS)   // 128
#define THREADS 128            // 4 warps, each owns 16 rows

// weight fragment image: per chunk, uint2 entries
//   W1: [h(2)][ks(6)][nt(8)][lane(32)]  -> 3072 uint2
//   W2: [h(2)][ks(4)][nt(8)][lane(32)]  -> 2048 uint2, at offset 3072
#define WCH_U2 5120
#define W2_OFF 3072
#define WCH_B  (WCH_U2 * 8)    // 40960 bytes per chunk

// smem layout (bytes): 3-slot weight ring + consts
#define SM_W   0                          // 3 * 40960 = 122880
#define SM_W0  (3 * WCH_B)                // 122880
#define SM_B1  (SM_W0 + 2048)
#define SM_B2  (SM_B1 + 2048)
#define SM_TH  (SM_B2 + 256)
#define SMEM_BYTES (SM_TH + 256)          // 127488

__device__ __align__(16) uint2 gWf[8][WCH_U2];

struct TrueC  { static constexpr bool value = true;  };
struct FalseC { static constexpr bool value = false; };

// ---------------- helpers ----------------
__device__ __forceinline__ float ftanh(float x) {
    float y; asm("tanh.approx.f32 %0, %1;" : "=f"(y) : "f"(x)); return y;
}
__device__ __forceinline__ void cp16(uint32_t dst, const void* src) {
    asm volatile("cp.async.cg.shared.global [%0], [%1], 16;" :: "r"(dst), "l"(src));
}
#define CP_COMMIT() asm volatile("cp.async.commit_group;" ::: "memory")
#define CP_WAIT0()  asm volatile("cp.async.wait_group 0;" ::: "memory")

// split two fp32 (xe = even-k, xo = odd-k) into bf16x2 hi and lo words, even in low half
__device__ __forceinline__ void split_pair(float xe, float xo, uint32_t& whi, uint32_t& wlo) {
    uint32_t h;
    asm("cvt.rn.bf16x2.f32 %0, %1, %2;" : "=r"(h) : "f"(xo), "f"(xe));
    float fe = __uint_as_float(h << 16);
    float fo = __uint_as_float(h & 0xFFFF0000u);
    uint32_t lw;
    asm("cvt.rn.bf16x2.f32 %0, %1, %2;" : "=r"(lw) : "f"(xo - fo), "f"(xe - fe));
    whi = h; wlo = lw;
}

__device__ __forceinline__ void mma16816(float d[4],
    uint32_t a0, uint32_t a1, uint32_t a2, uint32_t a3, uint2 b) {
    asm volatile(
        "mma.sync.aligned.m16n8k16.row.col.f32.bf16.bf16.f32 "
        "{%0,%1,%2,%3}, {%4,%5,%6,%7}, {%8,%9}, {%0,%1,%2,%3};"
        : "+f"(d[0]), "+f"(d[1]), "+f"(d[2]), "+f"(d[3])
        : "r"(a0), "r"(a1), "r"(a2), "r"(a3), "r"(b.x), "r"(b.y));
}

// ---------------- setup: prepack weights into B-fragment order, bf16 hi/lo ----
__global__ void build_frags(const float* __restrict__ W1, const float* __restrict__ W2) {
    int tid = blockIdx.x * blockDim.x + threadIdx.x;
    int stride = gridDim.x * blockDim.x;

    for (int i = tid; i < 24576; i += stride) {
        int l  = i & 31;
        int nt = (i >> 5) & 7;
        int r8 = i >> 8;
        int ks = r8 % 6;
        int h  = (r8 / 6) & 1;
        int ch = i / 3072;
        int n  = ch * 64 + nt * 8 + (l >> 2);
        int k0 = ks * 16 + (l & 3) * 2;
        float v[4] = { W1[(size_t)(1 + k0) * 512 + n], W1[(size_t)(2 + k0) * 512 + n],
                       W1[(size_t)(9 + k0) * 512 + n], W1[(size_t)(10 + k0) * 512 + n] };
        uint32_t p[2];
        #pragma unroll
        for (int q = 0; q < 2; q++) {
            float a = v[2*q], bq = v[2*q + 1];
            if (h) {
                a  -= __bfloat162float(__float2bfloat16(a));
                bq -= __bfloat162float(__float2bfloat16(bq));
            }
            p[q] = (uint32_t)__bfloat16_as_ushort(__float2bfloat16(a))
                 | ((uint32_t)__bfloat16_as_ushort(__float2bfloat16(bq)) << 16);
        }
        gWf[ch][((h * 6 + ks) * 8 + nt) * 32 + l] = make_uint2(p[0], p[1]);
    }

    for (int i = tid; i < 16384; i += stride) {
        int l  = i & 31;
        int nt = (i >> 5) & 7;
        int r8 = i >> 8;
        int ks = r8 % 4;
        int h  = (r8 / 4) & 1;
        int ch = i / 2048;
        int n  = nt * 8 + (l >> 2);
        int k0 = ch * 64 + ks * 16 + (l & 3) * 2;
        float v[4] = { W2[(size_t)k0 * 64 + n],       W2[(size_t)(k0 + 1) * 64 + n],
                       W2[(size_t)(k0 + 8) * 64 + n], W2[(size_t)(k0 + 9) * 64 + n] };
        uint32_t p[2];
        #pragma unroll
        for (int q = 0; q < 2; q++) {
            float a = v[2*q], bq = v[2*q + 1];
            if (h) {
                a  -= __bfloat162float(__float2bfloat16(a));
                bq -= __bfloat162float(__float2bfloat16(bq));
            }
            p[q] = (uint32_t)__bfloat16_as_ushort(__float2bfloat16(a))
                 | ((uint32_t)__bfloat16_as_ushort(__float2bfloat16(bq)) << 16);
        }
        gWf[ch][W2_OFF + ((h * 4 + ks) * 8 + nt) * 32 + l] = make_uint2(p[0], p[1]);
    }
}

// ---------------- main rollout: intra-warp pipelined bf16 MMA ----------------
__global__ void __launch_bounds__(THREADS, 1) rollout_mma(
    const float* __restrict__ X0, const float* __restrict__ V0,
    const float* __restrict__ Y,  const float* __restrict__ theta,
    const float* __restrict__ W1, const float* __restrict__ b1,
    const float* __restrict__ W2, const float* __restrict__ b2,
    const float* __restrict__ noise, const int* __restrict__ obs_index,
    float* __restrict__ out)
{
    extern __shared__ __align__(16) unsigned char smem[];
    uint2* sW  = (uint2*)(smem + SM_W);
    float* sW0 = (float*)(smem + SM_W0);
    float* sB1 = (float*)(smem + SM_B1);
    float* sB2 = (float*)(smem + SM_B2);
    float* sTH = (float*)(smem + SM_TH);
    const uint32_t sb = (uint32_t)__cvta_generic_to_shared(smem);

    const int tid = threadIdx.x;
    const int l = tid & 31;
    const int w = tid >> 5;
    const int g = l >> 2, c = l & 3;
    const int row0 = blockIdx.x * CTA_ROWS;
    const int rA = row0 + w * 16 + g;
    const int rB = rA + 8;

    const float dt = 1.0f / (float)Mm;
    const float sqdt = sqrtf(dt);
    const int obs = *obs_index;

    for (int i = tid; i < 512; i += THREADS) { sW0[i] = W1[i]; sB1[i] = b1[i]; }
    if (tid < 64) { sB2[tid] = b2[tid]; sTH[tid] = theta[tid]; }

    // X fp32 state, fragment-distributed
    float X[8][4];
    #pragma unroll
    for (int j = 0; j < 8; j++) {
        int col = c * 2 + 8 * j;
        float2 va = *(const float2*)(X0 + (size_t)rA * 64 + col);
        float2 vb = *(const float2*)(X0 + (size_t)rB * 64 + col);
        X[j][0] = va.x; X[j][1] = va.y; X[j][2] = vb.x; X[j][3] = vb.y;
    }

    // Y A-fragments (static): GEMM1 k-steps 4,5
    uint32_t Yhi[2][4], Ylo[2][4];
    #pragma unroll
    for (int ks = 0; ks < 2; ks++)
        #pragma unroll
        for (int r = 0; r < 2; r++) {
            int yc = ks * 16 + c * 2 + r * 8;
            float2 ya = *(const float2*)(Y + (size_t)rA * 32 + (size_t)obs * 32 + yc);
            float2 yb = *(const float2*)(Y + (size_t)rB * 32 + (size_t)obs * 32 + yc);
            split_pair(ya.x, ya.y, Yhi[ks][2*r],     Ylo[ks][2*r]);
            split_pair(yb.x, yb.y, Yhi[ks][2*r + 1], Ylo[ks][2*r + 1]);
        }

    uint32_t Xhi[4][4], Xlo[4][4];
    auto build_xfrags = [&]() {
        #pragma unroll
        for (int ks = 0; ks < 4; ks++) {
            split_pair(X[2*ks][0],     X[2*ks][1],     Xhi[ks][0], Xlo[ks][0]);
            split_pair(X[2*ks][2],     X[2*ks][3],     Xhi[ks][1], Xlo[ks][1]);
            split_pair(X[2*ks + 1][0], X[2*ks + 1][1], Xhi[ks][2], Xlo[ks][2]);
            split_pair(X[2*ks + 1][2], X[2*ks + 1][3], Xhi[ks][3], Xlo[ks][3]);
        }
    };
    build_xfrags();

    float vA = 0.0f, vB = 0.0f;
    float D2[8][4];
    float s_cur = 0.0f;
    float C1A[8][4], C1B[8][4];

    // ---- reusable pieces (captured by reference) ----
    // one GEMM1 k-step into C1 (term-outer: independent MMA chains back-to-back)
    auto g1k = [&](float (&C1)[8][4], const uint2* wb, int ks) {
        uint32_t AH[4], AL[4];
        #pragma unroll
        for (int q = 0; q < 4; q++) {
            AH[q] = (ks < 4) ? Xhi[ks & 3][q] : Yhi[ks & 1][q];
            AL[q] = (ks < 4) ? Xlo[ks & 3][q] : Ylo[ks & 1][q];
        }
        uint2 bh[8];
        #pragma unroll
        for (int nt = 0; nt < 8; nt++) bh[nt] = wb[(ks * 8 + nt) * 32 + l];
        #pragma unroll
        for (int nt = 0; nt < 8; nt++) mma16816(C1[nt], AH[0], AH[1], AH[2], AH[3], bh[nt]);
        #pragma unroll
        for (int nt = 0; nt < 8; nt++) mma16816(C1[nt], AL[0], AL[1], AL[2], AL[3], bh[nt]);
        uint2 bl[8];
        #pragma unroll
        for (int nt = 0; nt < 8; nt++) bl[nt] = wb[((6 + ks) * 8 + nt) * 32 + l];
        #pragma unroll
        for (int nt = 0; nt < 8; nt++) mma16816(C1[nt], AH[0], AH[1], AH[2], AH[3], bl[nt]);
    };

    auto tanhsplit = [&](float (&C1c)[8][4], int ch, int ks2,
                         uint32_t (&ah)[4], uint32_t (&al)[4]) {
        int col0 = ch * 64 + ks2 * 16 + c * 2;
        float2 w0a = *(const float2*)&sW0[col0];
        float2 b1a = *(const float2*)&sB1[col0];
        float2 w0b = *(const float2*)&sW0[col0 + 8];
        float2 b1b = *(const float2*)&sB1[col0 + 8];
        float hb0 = fmaf(s_cur, w0a.x, b1a.x), hb1 = fmaf(s_cur, w0a.y, b1a.y);
        float hb2 = fmaf(s_cur, w0b.x, b1b.x), hb3 = fmaf(s_cur, w0b.y, b1b.y);
        float h00 = ftanh(C1c[2*ks2][0] + hb0), h01 = ftanh(C1c[2*ks2][1] + hb1);
        float h02 = ftanh(C1c[2*ks2][2] + hb0), h03 = ftanh(C1c[2*ks2][3] + hb1);
        float h10 = ftanh(C1c[2*ks2+1][0] + hb2), h11 = ftanh(C1c[2*ks2+1][1] + hb3);
        float h12 = ftanh(C1c[2*ks2+1][2] + hb2), h13 = ftanh(C1c[2*ks2+1][3] + hb3);
        split_pair(h00, h01, ah[0], al[0]);
        split_pair(h02, h03, ah[1], al[1]);
        split_pair(h10, h11, ah[2], al[2]);
        split_pair(h12, h13, ah[3], al[3]);
    };

    auto mma2 = [&](const uint2* wb, int ks2,
                    const uint32_t (&ah)[4], const uint32_t (&al)[4]) {
        uint2 bh[8];
        #pragma unroll
        for (int nt = 0; nt < 8; nt++) bh[nt] = wb[W2_OFF + (ks2 * 8 + nt) * 32 + l];
        #pragma unroll
        for (int nt = 0; nt < 8; nt++) mma16816(D2[nt], ah[0], ah[1], ah[2], ah[3], bh[nt]);
        #pragma unroll
        for (int nt = 0; nt < 8; nt++) mma16816(D2[nt], al[0], al[1], al[2], al[3], bh[nt]);
        uint2 bl[8];
        #pragma unroll
        for (int nt = 0; nt < 8; nt++) bl[nt] = wb[W2_OFF + ((4 + ks2) * 8 + nt) * 32 + l];
        #pragma unroll
        for (int nt = 0; nt < 8; nt++) mma16816(D2[nt], ah[0], ah[1], ah[2], ah[3], bl[nt]);
    };

    // chunk body: epilogue(ch) interleaved with GEMM1(ch+1) into C1n
    auto body = [&](auto dn, float (&C1c)[8][4], float (&C1n)[8][4],
                    const uint2* wbc, const uint2* wbn, int ch) {
        constexpr bool DN = decltype(dn)::value;
        if constexpr (DN) {
            #pragma unroll
            for (int nt = 0; nt < 8; nt++)
                #pragma unroll
                for (int q = 0; q < 4; q++) C1n[nt][q] = 0.0f;
        }
        uint32_t ah[4], al[4];
        tanhsplit(C1c, ch, 0, ah, al);
        if constexpr (DN) g1k(C1n, wbn, 0);
        mma2(wbc, 0, ah, al);
        if constexpr (DN) g1k(C1n, wbn, 1);
        tanhsplit(C1c, ch, 1, ah, al);
        if constexpr (DN) g1k(C1n, wbn, 2);
        mma2(wbc, 1, ah, al);
        tanhsplit(C1c, ch, 2, ah, al);
        if constexpr (DN) g1k(C1n, wbn, 3);
        mma2(wbc, 2, ah, al);
        if constexpr (DN) g1k(C1n, wbn, 4);
        tanhsplit(C1c, ch, 3, ah, al);
        if constexpr (DN) g1k(C1n, wbn, 5);
        mma2(wbc, 3, ah, al);
    };

    auto pf = [&](int img, int slot) {
        const uint2* src = gWf[img];
        uint32_t dst = sb + SM_W + (uint32_t)slot * (uint32_t)WCH_B;
        for (int i = tid; i < WCH_U2 / 2; i += THREADS) cp16(dst + i * 16, src + i * 2);
        CP_COMMIT();
    };

    __syncthreads();      // consts staged

    // prologue: prefetch chunks 0 and 1 into slots 0 and 1
    pf(0, 0);
    pf(1, 1);

    float2 nA[8], nB[8];

    for (int m = 0; m < Mm; m++) {
        s_cur = (float)m * dt;
        #pragma unroll
        for (int nt = 0; nt < 8; nt++)
            #pragma unroll
            for (int q = 0; q < 4; q++) D2[nt][q] = 0.0f;

        const int gc0 = m * 8;

        for (int chp = 0; chp < 4; chp++) {
            const int ge = gc0 + 2 * chp;          // even global chunk
            // ---- even chunk iteration ----
            CP_WAIT0();
            __syncthreads();                        // slot (ge+2)%3 free, slot (ge+1)%3 loaded
            pf((ge + 2) & 7, (ge + 2) % 3);
            const uint2* wbc0 = sW + (ge % 3) * WCH_U2;
            const uint2* wbn0 = sW + ((ge + 1) % 3) * WCH_U2;
            if (chp == 0) {                         // serial GEMM1 for chunk 0 (needs new X)
                #pragma unroll
                for (int nt = 0; nt < 8; nt++)
                    #pragma unroll
                    for (int q = 0; q < 4; q++) C1A[nt][q] = 0.0f;
                #pragma unroll
                for (int ks = 0; ks < 6; ks++) g1k(C1A, wbc0, ks);
            }
            body(TrueC{}, C1A, C1B, wbc0, wbn0, 2 * chp);

            // ---- odd chunk iteration ----
            CP_WAIT0();
            __syncthreads();
            pf((ge + 3) & 7, (ge + 3) % 3);
            const uint2* wbc1 = sW + ((ge + 1) % 3) * WCH_U2;
            const uint2* wbn1 = sW + ((ge + 2) % 3) * WCH_U2;
            if (chp < 3) {
                body(TrueC{}, C1B, C1A, wbc1, wbn1, 2 * chp + 1);
            } else {
                // issue noise LDGs so DRAM latency hides behind chunk 7's body
                #pragma unroll
                for (int nt = 0; nt < 8; nt++) {
                    int col = c * 2 + 8 * nt;
                    nA[nt] = *(const float2*)(noise + ((size_t)m * Nn + rA) * 64 + col);
                    nB[nt] = *(const float2*)(noise + ((size_t)m * Nn + rB) * 64 + col);
                }
                body(FalseC{}, C1B, C1A, wbc1, wbn1, 7);
            }
        }

        // ---- step epilogue: Z -> V, X update ----
        #pragma unroll
        for (int nt = 0; nt < 8; nt++) {
            int col = c * 2 + 8 * nt;
            float2 b2v = *(const float2*)&sB2[col];
            float2 thv = *(const float2*)&sTH[col];
            float z0 = D2[nt][0] + b2v.x, z1 = D2[nt][1] + b2v.y;
            float z2 = D2[nt][2] + b2v.x, z3 = D2[nt][3] + b2v.y;
            float wa0 = sqdt * nA[nt].x, wa1 = sqdt * nA[nt].y;
            float wb0 = sqdt * nB[nt].x, wb1 = sqdt * nB[nt].y;
            vA += z0 * wa0 + z1 * wa1 - 0.5f * dt * (z0 * z0 + z1 * z1);
            vB += z2 * wb0 + z3 * wb1 - 0.5f * dt * (z2 * z2 + z3 * z3);
            X[nt][0] += dt * (thv.x - X[nt][0] - z0) + wa0;
            X[nt][1] += dt * (thv.y - X[nt][1] - z1) + wa1;
            X[nt][2] += dt * (thv.x - X[nt][2] - z2) + wb0;
            X[nt][3] += dt * (thv.y - X[nt][3] - z3) + wb1;
        }
        build_xfrags();
    }

    // ---- output ----
    #pragma unroll
    for (int nt = 0; nt < 8; nt++) {
        int col = c * 2 + 8 * nt;
        *(float2*)(out + (size_t)rA * 64 + col) = make_float2(X[nt][0], X[nt][1]);
        *(float2*)(out + (size_t)rB * 64 + col) = make_float2(X[nt][2], X[nt][3]);
    }
    vA += __shfl_down_sync(0xffffffffu, vA, 2, 4);
    vA += __shfl_down_sync(0xffffffffu, vA, 1, 4);
    vB += __shfl_down_sync(0xffffffffu, vB, 2, 4);
    vB += __shfl_down_sync(0xffffffffu, vB, 1, 4);
    if (c == 0) {
        out[(size_t)Nn * 64 + rA] = V0[rA] + vA;
        out[(size_t)Nn * 64 + rB] = V0[rB] + vB;
    }
    CP_WAIT0();     // drain trailing prefetches before exit
}

extern "C" void kernel_launch(void* const* d_in, const int* in_sizes, int n_in,
                              void* d_out, int out_size)
{
    (void)in_sizes; (void)n_in; (void)out_size;
    cudaFuncSetAttribute(rollout_mma,
                         cudaFuncAttributeMaxDynamicSharedMemorySize, SMEM_BYTES);

    build_frags<<<64, 256>>>((const float*)d_in[4], (const float*)d_in[6]);
    rollout_mma<<<GRID, THREADS, SMEM_BYTES>>>(
        (const float*)d_in[0], (const float*)d_in[1], (const float*)d_in[2],
        (const float*)d_in[3], (const float*)d_in[4], (const float*)d_in[5],
        (const float*)d_in[6], (const float*)d_in[7], (const float*)d_in[8],
        (const int*)d_in[9],   (float*)d_out);
}